// round 1
// baseline (speedup 1.0000x reference)
#include <cuda_runtime.h>
#include <cuda_bf16.h>
#include <cfloat>
#include <math.h>

#define NN 200000
#define EE 3200000
#define BB 2000
#define NPG 100
#define HH 32
#define KK 60
#define DD 97

// ---------------- device scratch (no allocs allowed) ----------------
__device__ float g_deg[NN];
__device__ float g_dis[NN];
__device__ int   g_cnt[NN];
__device__ int   g_off[NN];
__device__ int   g_cur[NN];
__device__ int   g_csr_src[EE];
__device__ float g_csr_norm[EE];
__device__ float g_h [NN * 32];   // temp x@W (also reused as scalar buffer layer 3)
__device__ float g_h1[NN * 32];
__device__ float g_h2[NN * 32];
__device__ float g_h3[NN * 32];
__device__ float g_h4[NN];
__device__ int   g_bsum[256];

// ---------------- CSR build ----------------
__global__ void k_init() {
    int i = blockIdx.x * blockDim.x + threadIdx.x;
    if (i < NN) { g_deg[i] = 1.0f; g_cnt[i] = 0; }  // self loop weight 1
}

__global__ void k_hist(const int* __restrict__ ei, const float* __restrict__ ew) {
    int e = blockIdx.x * blockDim.x + threadIdx.x;
    if (e < EE) {
        int dst = ei[EE + e];
        atomicAdd(&g_deg[dst], ew[e]);
        atomicAdd(&g_cnt[dst], 1);
    }
}

__global__ void k_dis() {
    int i = blockIdx.x * blockDim.x + threadIdx.x;
    if (i < NN) g_dis[i] = rsqrtf(g_deg[i]);
}

// block-level exclusive scan (1024/block) producing per-block sums
__global__ void k_scan1() {
    __shared__ int sh[1024];
    int tid = threadIdx.x;
    int i = blockIdx.x * 1024 + tid;
    int v = (i < NN) ? g_cnt[i] : 0;
    sh[tid] = v;
    __syncthreads();
    for (int ofs = 1; ofs < 1024; ofs <<= 1) {
        int t = (tid >= ofs) ? sh[tid - ofs] : 0;
        __syncthreads();
        sh[tid] += t;
        __syncthreads();
    }
    int incl = sh[tid];
    if (i < NN) g_off[i] = incl - v;
    if (tid == 1023) g_bsum[blockIdx.x] = incl;
}

__global__ void k_scan2(int nb) {
    __shared__ int sh[256];
    int tid = threadIdx.x;
    int v = (tid < nb) ? g_bsum[tid] : 0;
    sh[tid] = v;
    __syncthreads();
    for (int ofs = 1; ofs < 256; ofs <<= 1) {
        int t = (tid >= ofs) ? sh[tid - ofs] : 0;
        __syncthreads();
        sh[tid] += t;
        __syncthreads();
    }
    if (tid < nb) g_bsum[tid] = sh[tid] - v;  // exclusive
}

__global__ void k_scan3() {
    int tid = threadIdx.x;
    int i = blockIdx.x * 1024 + tid;
    if (i < NN) {
        int o = g_off[i] + g_bsum[blockIdx.x];
        g_off[i] = o;
        g_cur[i] = o;
    }
}

__global__ void k_fill(const int* __restrict__ ei, const float* __restrict__ ew) {
    int e = blockIdx.x * blockDim.x + threadIdx.x;
    if (e < EE) {
        int src = ei[e];
        int dst = ei[EE + e];
        int pos = atomicAdd(&g_cur[dst], 1);
        g_csr_src[pos]  = src;
        g_csr_norm[pos] = g_dis[src] * ew[e] * g_dis[dst];
    }
}

// ---------------- GCN layers ----------------
// layer 0: fused embedding gather + [N,96]@[96,32]
__global__ void k_mm0(const int* __restrict__ w, const int* __restrict__ z1,
                      const int* __restrict__ z2,
                      const float* __restrict__ emb_w, const float* __restrict__ emb_z1,
                      const float* __restrict__ emb_z2, const float* __restrict__ W0) {
    __shared__ float Ws[96 * 32];
    for (int i = threadIdx.x; i < 96 * 32; i += blockDim.x) Ws[i] = W0[i];
    __syncthreads();
    int lane = threadIdx.x & 31;
    int warp = (blockIdx.x * blockDim.x + threadIdx.x) >> 5;
    int nwarps = (gridDim.x * blockDim.x) >> 5;
    for (int n = warp; n < NN; n += nwarps) {
        float r0 = emb_w [w [n] * 32 + lane];
        float r1 = emb_z1[z1[n] * 32 + lane];
        float r2 = emb_z2[z2[n] * 32 + lane];
        float acc = 0.f;
#pragma unroll
        for (int k = 0; k < 32; k++) acc += __shfl_sync(0xffffffffu, r0, k) * Ws[k * 32 + lane];
#pragma unroll
        for (int k = 0; k < 32; k++) acc += __shfl_sync(0xffffffffu, r1, k) * Ws[(32 + k) * 32 + lane];
#pragma unroll
        for (int k = 0; k < 32; k++) acc += __shfl_sync(0xffffffffu, r2, k) * Ws[(64 + k) * 32 + lane];
        g_h[n * 32 + lane] = acc;
    }
}

// [N,32]@[32,32]
__global__ void k_mm32(const float* __restrict__ x, const float* __restrict__ W) {
    __shared__ float Ws[32 * 32];
    for (int i = threadIdx.x; i < 32 * 32; i += blockDim.x) Ws[i] = W[i];
    __syncthreads();
    int lane = threadIdx.x & 31;
    int warp = (blockIdx.x * blockDim.x + threadIdx.x) >> 5;
    int nwarps = (gridDim.x * blockDim.x) >> 5;
    for (int n = warp; n < NN; n += nwarps) {
        float r = x[n * 32 + lane];
        float acc = 0.f;
#pragma unroll
        for (int k = 0; k < 32; k++) acc += __shfl_sync(0xffffffffu, r, k) * Ws[k * 32 + lane];
        g_h[n * 32 + lane] = acc;
    }
}

// [N,32]@[32,1] -> g_h[n]
__global__ void k_mm1(const float* __restrict__ x, const float* __restrict__ W3) {
    int lane = threadIdx.x & 31;
    int warp = (blockIdx.x * blockDim.x + threadIdx.x) >> 5;
    int nwarps = (gridDim.x * blockDim.x) >> 5;
    for (int n = warp; n < NN; n += nwarps) {
        float v = x[n * 32 + lane] * W3[lane];
#pragma unroll
        for (int o = 16; o > 0; o >>= 1) v += __shfl_down_sync(0xffffffffu, v, o);
        if (lane == 0) g_h[n] = v;
    }
}

// aggregate 32-channel h over CSR, + bias, tanh
__global__ void k_agg32(const float* __restrict__ bias, float* __restrict__ out) {
    int lane = threadIdx.x & 31;
    int warp = (blockIdx.x * blockDim.x + threadIdx.x) >> 5;
    int nwarps = (gridDim.x * blockDim.x) >> 5;
    for (int n = warp; n < NN; n += nwarps) {
        float dn = g_dis[n];
        float acc = dn * dn * g_h[n * 32 + lane];
        int s0 = g_off[n], e0 = s0 + g_cnt[n];
        for (int i = s0; i < e0; i++) {
            int s = g_csr_src[i];
            acc += g_csr_norm[i] * g_h[s * 32 + lane];
        }
        out[n * 32 + lane] = tanhf(acc + bias[lane]);
    }
}

// aggregate scalar (layer 3)
__global__ void k_agg1(const float* __restrict__ b3) {
    int lane = threadIdx.x & 31;
    int warp = (blockIdx.x * blockDim.x + threadIdx.x) >> 5;
    int nwarps = (gridDim.x * blockDim.x) >> 5;
    for (int n = warp; n < NN; n += nwarps) {
        int s0 = g_off[n], e0 = s0 + g_cnt[n];
        float acc = 0.f;
        for (int i = s0 + lane; i < e0; i += 32)
            acc += g_csr_norm[i] * g_h[g_csr_src[i]];
#pragma unroll
        for (int o = 16; o > 0; o >>= 1) acc += __shfl_down_sync(0xffffffffu, acc, o);
        if (lane == 0) {
            float dn = g_dis[n];
            g_h4[n] = tanhf(acc + dn * dn * g_h[n] + b3[0]);
        }
    }
}

// ---------------- fused tail: sort-pool + conv1 + maxpool + conv2 + mlp ----------------
__global__ void k_tail(const float* __restrict__ c1W, const float* __restrict__ c1b,
                       const float* __restrict__ c2W, const float* __restrict__ c2b,
                       const float* __restrict__ l1W, const float* __restrict__ l1b,
                       const float* __restrict__ l2W, const float* __restrict__ l2b,
                       float* __restrict__ out) {
    __shared__ float s_vals[128];
    __shared__ int   s_idx[128];
    __shared__ float s_xs[KK * DD];     // 60*97
    __shared__ float s_w[2560];         // c1W (1552) then c2W (2560)
    __shared__ float s_t1[16 * KK];     // 960
    __shared__ float s_pool[16 * 30];   // 480
    __shared__ float s_flat[832];
    __shared__ float s_red[4];

    int b = blockIdx.x;
    int t = threadIdx.x;
    int g0 = b * NPG;

    // --- sort keys (descending value, ascending index for jnp.argsort stability) ---
    float v = (t < NPG) ? g_h4[g0 + t] : -FLT_MAX;
    int   id = (t < NPG) ? t : 0x7fffffff;
    s_vals[t] = v; s_idx[t] = id;
    __syncthreads();
    for (int k = 2; k <= 128; k <<= 1) {
        for (int j = k >> 1; j > 0; j >>= 1) {
            int ixj = t ^ j;
            if (ixj > t) {
                float va = s_vals[t],  vb = s_vals[ixj];
                int   ia = s_idx[t],   ib = s_idx[ixj];
                bool before = (va > vb) || (va == vb && ia < ib);
                bool up = ((t & k) == 0);
                if (up ? !before : before) {
                    s_vals[t] = vb; s_vals[ixj] = va;
                    s_idx[t]  = ib; s_idx[ixj]  = ia;
                }
            }
            __syncthreads();
        }
    }

    // --- gather top-K features into shared [K][D] ---
    for (int q = t; q < KK * DD; q += 128) {
        int kk = q / DD, dd = q - kk * DD;
        int node = g0 + s_idx[kk];
        float val;
        if      (dd < 32) val = g_h1[node * 32 + dd];
        else if (dd < 64) val = g_h2[node * 32 + dd - 32];
        else if (dd < 96) val = g_h3[node * 32 + dd - 64];
        else              val = g_h4[node];
        s_xs[q] = val;
    }
    for (int q = t; q < 16 * DD; q += 128) s_w[q] = c1W[q];
    __syncthreads();

    // --- conv1: t1[o][k] = relu(sum_d xs[k][d] * c1W[o][d] + c1b[o]) ---
    for (int q = t; q < 16 * KK; q += 128) {
        int o = q / KK, kk = q - o * KK;
        float acc = c1b[o];
        for (int dd = 0; dd < DD; dd++) acc += s_xs[kk * DD + dd] * s_w[o * DD + dd];
        s_t1[o * KK + kk] = fmaxf(acc, 0.f);
    }
    __syncthreads();

    // --- maxpool(2,2): pool[o][p] over 30, and stage c2W ---
    for (int q = t; q < 16 * 30; q += 128) {
        int o = q / 30, p = q - o * 30;
        s_pool[o * 30 + p] = fmaxf(s_t1[o * KK + 2 * p], s_t1[o * KK + 2 * p + 1]);
    }
    for (int q = t; q < 2560; q += 128) s_w[q] = c2W[q];
    __syncthreads();

    // --- conv2: flat[o*26+p] = relu(sum_{i,tau} pool[i][p+tau]*c2W[o][i][tau] + c2b[o]) ---
    for (int q = t; q < 832; q += 128) {
        int o = q / 26, p = q - o * 26;
        float acc = c2b[o];
        for (int i = 0; i < 16; i++) {
#pragma unroll
            for (int tt = 0; tt < 5; tt++)
                acc += s_pool[i * 30 + p + tt] * s_w[o * 80 + i * 5 + tt];
        }
        s_flat[o * 26 + p] = fmaxf(acc, 0.f);
    }
    __syncthreads();

    // --- l1: y[t] = relu(flat @ l1W[:,t] + l1b[t]) ---
    float acc = l1b[t];
    for (int f = 0; f < 832; f++) acc += s_flat[f] * l1W[f * 128 + t];
    float y = fmaxf(acc, 0.f);

    // --- l2: scalar reduce ---
    float p = y * l2W[t];
#pragma unroll
    for (int o = 16; o > 0; o >>= 1) p += __shfl_down_sync(0xffffffffu, p, o);
    if ((t & 31) == 0) s_red[t >> 5] = p;
    __syncthreads();
    if (t == 0) out[b] = s_red[0] + s_red[1] + s_red[2] + s_red[3] + l2b[0];
}

// ---------------- launch ----------------
extern "C" void kernel_launch(void* const* d_in, const int* in_sizes, int n_in,
                              void* d_out, int out_size) {
    const int*   z1    = (const int*)  d_in[0];
    const int*   z2    = (const int*)  d_in[1];
    const int*   w     = (const int*)  d_in[2];
    const int*   ei    = (const int*)  d_in[3];
    // d_in[4] = batch (implicit: contiguous graphs of 100)
    const float* ew    = (const float*)d_in[5];
    const float* emb_w = (const float*)d_in[6];
    const float* emb_z1= (const float*)d_in[7];
    const float* emb_z2= (const float*)d_in[8];
    const float* W0 = (const float*)d_in[9];
    const float* b0 = (const float*)d_in[10];
    const float* W1 = (const float*)d_in[11];
    const float* b1 = (const float*)d_in[12];
    const float* W2 = (const float*)d_in[13];
    const float* b2 = (const float*)d_in[14];
    const float* W3 = (const float*)d_in[15];
    const float* b3 = (const float*)d_in[16];
    const float* c1W = (const float*)d_in[17];
    const float* c1b = (const float*)d_in[18];
    const float* c2W = (const float*)d_in[19];
    const float* c2b = (const float*)d_in[20];
    const float* l1W = (const float*)d_in[21];
    const float* l1b = (const float*)d_in[22];
    const float* l2W = (const float*)d_in[23];
    const float* l2b = (const float*)d_in[24];
    float* out = (float*)d_out;

    const int nb_n = (NN + 255) / 256;
    const int nb_e = (EE + 255) / 256;
    const int nb_scan = (NN + 1023) / 1024;   // 196
    const int GRID = 1480;                    // 10 blocks/SM, grid-stride warps

    // device pointers to layer temporaries
    float *h1, *h2, *h3;
    cudaGetSymbolAddress((void**)&h1, g_h1);
    cudaGetSymbolAddress((void**)&h2, g_h2);
    cudaGetSymbolAddress((void**)&h3, g_h3);

    // CSR build
    k_init<<<nb_n, 256>>>();
    k_hist<<<nb_e, 256>>>(ei, ew);
    k_dis<<<nb_n, 256>>>();
    k_scan1<<<nb_scan, 1024>>>();
    k_scan2<<<1, 256>>>(nb_scan);
    k_scan3<<<nb_scan, 1024>>>();
    k_fill<<<nb_e, 256>>>(ei, ew);

    // GCN stack
    k_mm0  <<<GRID, 256>>>(w, z1, z2, emb_w, emb_z1, emb_z2, W0);
    k_agg32<<<GRID, 256>>>(b0, h1);
    k_mm32 <<<GRID, 256>>>(h1, W1);
    k_agg32<<<GRID, 256>>>(b1, h2);
    k_mm32 <<<GRID, 256>>>(h2, W2);
    k_agg32<<<GRID, 256>>>(b2, h3);
    k_mm1  <<<GRID, 256>>>(h3, W3);
    k_agg1 <<<GRID, 256>>>(b3);

    // sort-pool + convs + mlp
    k_tail<<<BB, 128>>>(c1W, c1b, c2W, c2b, l1W, l1b, l2W, l2b, out);
}